// round 9
// baseline (speedup 1.0000x reference)
#include <cuda_runtime.h>
#include <cuda_bf16.h>
#include <math.h>
#include <stdint.h>

#define B_  2
#define L_  768
#define E_  768
#define H_  12
#define DH_ 64
#define D_  8
#define DS_ 8
#define INV_SQRT_DS 0.35355339059327373f
#define ALPHA_ 2.5f

// ---------------- scratch (static device globals; no allocation) -------------
__device__ float  g_Q[B_*H_*L_*DH_];
__device__ float  g_K[B_*H_*L_*DH_];
__device__ float  g_V[B_*H_*L_*DH_];
__device__ float  g_S[B_*H_*D_*L_];      // per (b,h,d,q): softmax denom (m=0)
__device__ double g_acc[B_*D_*4];        // sums over (h,q): var, max, hhi, ent
__device__ float  g_w[B_*D_];            // depth gate weights

// bf16 hi/lo splits for tensor-core projections
__device__ __nv_bfloat16 g_Xh[(size_t)B_*L_*E_];
__device__ __nv_bfloat16 g_Xl[(size_t)B_*L_*E_];
__device__ __nv_bfloat16 g_Wh[(size_t)3*E_*E_];
__device__ __nv_bfloat16 g_Wl[(size_t)3*E_*E_];

__device__ __forceinline__ uint32_t smem_u32(const void* p) {
    uint32_t a;
    asm("{ .reg .u64 t; cvta.to.shared.u64 t, %1; cvt.u32.u64 %0, t; }"
        : "=r"(a) : "l"(p));
    return a;
}
#define CP_ASYNC16(sm, gp) \
    asm volatile("cp.async.cg.shared.global [%0], [%1], 16;" :: "r"(sm), "l"(gp))
#define CP_COMMIT() asm volatile("cp.async.commit_group;" ::: "memory")
#define CP_WAIT1()  asm volatile("cp.async.wait_group 1;" ::: "memory")

// ============================================================================
// K0: split fp32 X and W into bf16 hi/lo; also zero g_acc.
// ============================================================================
#define NX4 ((B_*L_*E_) / 4)
#define NW4 ((E_*E_) / 4)

__global__ __launch_bounds__(256) void split_kernel(
    const float* __restrict__ X,
    const float* __restrict__ Wq, const float* __restrict__ Wk,
    const float* __restrict__ Wv)
{
    int idx = blockIdx.x * blockDim.x + threadIdx.x;
    if (blockIdx.x == 0 && threadIdx.x < B_*D_*4) g_acc[threadIdx.x] = 0.0;
    if (idx >= NX4 + 3 * NW4) return;

    const float* src;
    __nv_bfloat16 *dh, *dl;
    int off;
    if (idx < NX4) {
        src = X; dh = g_Xh; dl = g_Xl; off = idx * 4;
    } else {
        int j = idx - NX4;
        int w = j / NW4;
        off = (j - w * NW4) * 4;
        src = (w == 0) ? Wq : (w == 1) ? Wk : Wv;
        dh = g_Wh + (size_t)w * E_ * E_;
        dl = g_Wl + (size_t)w * E_ * E_;
    }
    float4 v = *reinterpret_cast<const float4*>(&src[off]);
    float f[4] = {v.x, v.y, v.z, v.w};
    ushort4 uh, ul;
    unsigned short* ph = &uh.x;
    unsigned short* pl = &ul.x;
    #pragma unroll
    for (int i = 0; i < 4; i++) {
        __nv_bfloat16 hi = __float2bfloat16(f[i]);
        __nv_bfloat16 lo = __float2bfloat16(f[i] - __bfloat162float(hi));
        ph[i] = __bfloat16_as_ushort(hi);
        pl[i] = __bfloat16_as_ushort(lo);
    }
    *reinterpret_cast<ushort4*>(&dh[off]) = uh;
    *reinterpret_cast<ushort4*>(&dl[off]) = ul;
}

// ============================================================================
// K1: mma.sync bf16 projection GEMM with 3-stage cp.async pipeline.
// C[1536,768] = [Xh|Xh|Xl] @ [[Wh],[Wl],[Wh]]  (K = 3*768, phase-indexed).
// CTA tile 128x128, 8 warps (4m x 2n), warp tile 32x64 = 2x8 m16n8k16.
// One __syncthreads per k-iter; loads overlap compute via cp.async.
// ============================================================================
#define SA 40      // A smem row stride (bf16): 80B = 5x16B -> aligned + conflict-free
#define SB 136     // B smem row stride (bf16): 272B = 17x16B
#define KITERS 72  // 2304 / 32
#define A_BYTES (128 * SA * 2)
#define B_BYTES (32 * SB * 2)
#define STG_BYTES (A_BYTES + B_BYTES)
#define PROJ_SMEM (3 * STG_BYTES)

__global__ __launch_bounds__(256) void proj_mma_kernel(
    const float* __restrict__ bq, const float* __restrict__ bk,
    const float* __restrict__ bv)
{
    extern __shared__ char smdyn[];

    const int t = threadIdx.x, warp = t >> 5, lane = t & 31;
    const int wm = warp & 3, wn = warp >> 2;
    const int z = blockIdx.z;
    const int row0 = blockIdx.y * 128, col0 = blockIdx.x * 128;

    const __nv_bfloat16* Wh = g_Wh + (size_t)z * E_ * E_;
    const __nv_bfloat16* Wl = g_Wl + (size_t)z * E_ * E_;
    const float* bias = (z == 0) ? bq : (z == 1) ? bk : bv;
    float* out = (z == 0) ? g_Q : (z == 1) ? g_K : g_V;

    // chunk mappings (16B granules)
    const int a_r0 = t >> 2,  a_c0 = (t & 3) * 8;           // + c=t+256: rows 64..127
    const int a_r1 = (t + 256) >> 2, a_c1 = ((t + 256) & 3) * 8;
    const int b_k0 = t >> 4,  b_n0 = (t & 15) * 8;
    const int b_k1 = (t + 256) >> 4, b_n1 = ((t + 256) & 15) * 8;

    auto issue_stage = [&](int it) {
        const int ph = it / 24;
        const int k768 = (it % 24) * 32;
        const __nv_bfloat16* Ap = (ph < 2) ? g_Xh : g_Xl;
        const __nv_bfloat16* Bp = (ph == 1) ? Wl : Wh;
        char* sa = smdyn + (it % 3) * STG_BYTES;
        char* sb = sa + A_BYTES;
        CP_ASYNC16(smem_u32(sa + (a_r0 * SA + a_c0) * 2),
                   &Ap[(size_t)(row0 + a_r0) * E_ + k768 + a_c0]);
        CP_ASYNC16(smem_u32(sa + (a_r1 * SA + a_c1) * 2),
                   &Ap[(size_t)(row0 + a_r1) * E_ + k768 + a_c1]);
        CP_ASYNC16(smem_u32(sb + (b_k0 * SB + b_n0) * 2),
                   &Bp[(size_t)(k768 + b_k0) * E_ + col0 + b_n0]);
        CP_ASYNC16(smem_u32(sb + (b_k1 * SB + b_n1) * 2),
                   &Bp[(size_t)(k768 + b_k1) * E_ + col0 + b_n1]);
    };

    float acc[2][8][4];
    #pragma unroll
    for (int mt = 0; mt < 2; mt++)
        #pragma unroll
        for (int nt = 0; nt < 8; nt++)
            #pragma unroll
            for (int i = 0; i < 4; i++) acc[mt][nt][i] = 0.f;

    issue_stage(0); CP_COMMIT();
    issue_stage(1); CP_COMMIT();

    for (int it = 0; it < KITERS; it++) {
        CP_WAIT1();
        __syncthreads();
        // issue next stage (overwrites buffer freed by compute(it-1), which all
        // threads finished before the barrier above)
        if (it + 2 < KITERS) { issue_stage(it + 2); CP_COMMIT(); }
        else                 { CP_COMMIT(); }   // empty group keeps accounting uniform

        const __nv_bfloat16* As =
            reinterpret_cast<const __nv_bfloat16*>(smdyn + (it % 3) * STG_BYTES);
        const __nv_bfloat16* Bs =
            reinterpret_cast<const __nv_bfloat16*>(smdyn + (it % 3) * STG_BYTES + A_BYTES);

        #pragma unroll
        for (int ks = 0; ks < 2; ks++) {
            uint32_t a[2][4];
            #pragma unroll
            for (int mt = 0; mt < 2; mt++) {
                uint32_t addr = smem_u32(
                    &As[(wm * 32 + mt * 16 + (lane & 15)) * SA + ks * 16 + (lane >> 4) * 8]);
                asm volatile("ldmatrix.sync.aligned.m8n8.x4.shared.b16 {%0,%1,%2,%3}, [%4];"
                    : "=r"(a[mt][0]), "=r"(a[mt][1]), "=r"(a[mt][2]), "=r"(a[mt][3])
                    : "r"(addr));
            }
            #pragma unroll
            for (int nt = 0; nt < 8; nt++) {
                uint32_t b0, b1;
                uint32_t baddr = smem_u32(
                    &Bs[(ks * 16 + (lane & 15)) * SB + wn * 64 + nt * 8]);
                asm volatile("ldmatrix.sync.aligned.m8n8.x2.trans.shared.b16 {%0,%1}, [%2];"
                    : "=r"(b0), "=r"(b1) : "r"(baddr));
                #pragma unroll
                for (int mt = 0; mt < 2; mt++) {
                    asm volatile(
                        "mma.sync.aligned.m16n8k16.row.col.f32.bf16.bf16.f32 "
                        "{%0,%1,%2,%3}, {%4,%5,%6,%7}, {%8,%9}, {%0,%1,%2,%3};"
                        : "+f"(acc[mt][nt][0]), "+f"(acc[mt][nt][1]),
                          "+f"(acc[mt][nt][2]), "+f"(acc[mt][nt][3])
                        : "r"(a[mt][0]), "r"(a[mt][1]), "r"(a[mt][2]), "r"(a[mt][3]),
                          "r"(b0), "r"(b1));
                }
            }
        }
        __syncthreads();
    }

    // epilogue: bias + store to [b,h,l,dh]
    #pragma unroll
    for (int mt = 0; mt < 2; mt++) {
        #pragma unroll
        for (int nt = 0; nt < 8; nt++) {
            int r = row0 + wm * 32 + mt * 16 + (lane >> 2);
            int c = col0 + wn * 64 + nt * 8 + (lane & 3) * 2;
            int h = c >> 6, dh = c & 63;
            float bz0 = bias[c], bz1 = bias[c + 1];
            #pragma unroll
            for (int half = 0; half < 2; half++) {
                int rr = r + half * 8;
                int b = rr / L_, l = rr % L_;
                float* op = &out[(size_t)((b * H_ + h) * L_ + l) * DH_ + dh];
                float2 v;
                v.x = acc[mt][nt][half * 2 + 0] + bz0;
                v.y = acc[mt][nt][half * 2 + 1] + bz1;
                *reinterpret_cast<float2*>(op) = v;
            }
        }
    }
}

// ============================================================================
// K2: branchless stats, m=0 for exp; true row max tracked for the max stat.
// ============================================================================
__global__ __launch_bounds__(256) void stats_kernel(const float* __restrict__ mask)
{
    __shared__ float sk[L_ * 12];
    __shared__ float sq[32 * 8];
    __shared__ float smask[L_];
    __shared__ float sred[8][4];

    const int t = threadIdx.x;
    const int bhd = blockIdx.x;
    const int d = bhd & 7;
    const int h = (bhd >> 3) % H_;
    const int b = bhd / (8 * H_);
    const int q0 = blockIdx.y * 32;

    const float* Kbase = &g_K[(size_t)(b * H_ + h) * L_ * DH_ + d * 8];

    for (int i = t; i < L_ * 2; i += 256) {
        int k = i >> 1, half = (i & 1) * 4;
        *reinterpret_cast<float4*>(&sk[k * 12 + half]) =
            *reinterpret_cast<const float4*>(&Kbase[(size_t)k * DH_ + half]);
    }
    sq[t] = g_Q[(size_t)((b * H_ + h) * L_ + q0 + (t >> 3)) * DH_ + d * 8 + (t & 7)];
    for (int i = t; i < L_; i += 256) smask[i] = mask[b * L_ + i];
    __syncthreads();

    const int warp = t >> 5, lane = t & 31;
    const int r0 = warp * 4;

    float qr[4][8];
    #pragma unroll
    for (int r = 0; r < 4; r++)
        #pragma unroll
        for (int s = 0; s < 8; s++) qr[r][s] = sq[(r0 + r) * 8 + s];

    float S[4]  = {0.f, 0.f, 0.f, 0.f};
    float E1[4] = {0.f, 0.f, 0.f, 0.f};
    float E2[4] = {0.f, 0.f, 0.f, 0.f};
    float M[4]  = {-1e30f, -1e30f, -1e30f, -1e30f};

    for (int kb = 0; kb < L_; kb += 32) {
        int k = kb + lane;
        float4 ka  = *reinterpret_cast<const float4*>(&sk[k * 12]);
        float4 kb4 = *reinterpret_cast<const float4*>(&sk[k * 12 + 4]);
        float mk = smask[k];
        #pragma unroll
        for (int r = 0; r < 4; r++) {
            float s = qr[r][0] * ka.x;
            s = fmaf(qr[r][1], ka.y, s);
            s = fmaf(qr[r][2], ka.z, s);
            s = fmaf(qr[r][3], ka.w, s);
            s = fmaf(qr[r][4], kb4.x, s);
            s = fmaf(qr[r][5], kb4.y, s);
            s = fmaf(qr[r][6], kb4.z, s);
            s = fmaf(qr[r][7], kb4.w, s);
            s = fmaf(s, INV_SQRT_DS, mk);
            float e = __expf(s);
            S[r]  += e;
            E1[r]  = fmaf(e, s, E1[r]);
            E2[r]  = fmaf(e, e, E2[r]);
            M[r]   = fmaxf(M[r], s);
        }
    }

    #pragma unroll
    for (int r = 0; r < 4; r++) {
        #pragma unroll
        for (int off = 16; off > 0; off >>= 1) {
            S[r]  += __shfl_xor_sync(0xffffffff, S[r],  off);
            E1[r] += __shfl_xor_sync(0xffffffff, E1[r], off);
            E2[r] += __shfl_xor_sync(0xffffffff, E2[r], off);
            M[r]   = fmaxf(M[r], __shfl_xor_sync(0xffffffff, M[r], off));
        }
    }

    if (lane == 0) {
        float psum[4] = {0.f, 0.f, 0.f, 0.f};
        #pragma unroll
        for (int r = 0; r < 4; r++) {
            int row  = q0 + r0 + r;
            int ridx = ((b * H_ + h) * D_ + d) * L_ + row;
            g_S[ridx] = S[r];
            float inv  = 1.0f / S[r];
            float maxp = __expf(M[r]) * inv;
            float hhi  = E2[r] * inv * inv;
            float var  = (hhi - (1.0f / (float)L_)) * (1.0f / (float)(L_ - 1));
            float ent  = __logf(S[r]) - E1[r] * inv;
            psum[0] += var; psum[1] += maxp; psum[2] += hhi; psum[3] += ent;
        }
        #pragma unroll
        for (int i = 0; i < 4; i++) sred[warp][i] = psum[i];
    }
    __syncthreads();
    if (t == 0) {
        double tot[4] = {0, 0, 0, 0};
        #pragma unroll
        for (int w = 0; w < 8; w++)
            #pragma unroll
            for (int i = 0; i < 4; i++) tot[i] += (double)sred[w][i];
        #pragma unroll
        for (int i = 0; i < 4; i++)
            atomicAdd(&g_acc[(b * D_ + d) * 4 + i], tot[i]);
    }
}

// ============================================================================
// K3: depth gate weights.
// ============================================================================
__global__ void weights_kernel()
{
    int lane = threadIdx.x;
    int b  = (lane >> 3) & 1;
    int dd = lane & 7;
    const float scale = 1.0f / (float)(H_ * L_);
    float st[4];
    #pragma unroll
    for (int i = 0; i < 4; i++)
        st[i] = (float)(g_acc[(b * D_ + dd) * 4 + i]) * scale;

    float n[4];
    #pragma unroll
    for (int i = 0; i < 4; i++) {
        float vmin = st[i], vmax = st[i];
        #pragma unroll
        for (int off = 1; off < 8; off <<= 1) {
            vmin = fminf(vmin, __shfl_xor_sync(0xffffffff, vmin, off));
            vmax = fmaxf(vmax, __shfl_xor_sync(0xffffffff, vmax, off));
        }
        n[i] = (st[i] - vmin) / fmaxf(vmax - vmin, 1e-12f);
    }
    float score = 0.5f * n[0] + 0.3f * n[1] + 0.2f * n[2] - 0.4f * n[3];
    float smax = score;
    #pragma unroll
    for (int off = 1; off < 8; off <<= 1)
        smax = fmaxf(smax, __shfl_xor_sync(0xffffffff, smax, off));
    float e = __expf(ALPHA_ * (score - smax));
    float ssum = e;
    #pragma unroll
    for (int off = 1; off < 8; off <<= 1)
        ssum += __shfl_xor_sync(0xffffffff, ssum, off);
    if (lane < 16) g_w[b * D_ + dd] = e / ssum;
}

// ============================================================================
// K4: register-blocked 4q x 4k score tile; m=0.
// ============================================================================
#define QT 32
#define KT 128
#define KPAD 68
#define APAD 132

__global__ __launch_bounds__(256, 2) void attn_kernel(
    const float* __restrict__ mask,
    float* __restrict__ out_ctx,
    float* __restrict__ out_attn)
{
    extern __shared__ float smem_[];
    float* sQ   = smem_;
    float* sMul = sQ   + QT * DH_;
    float* sK   = sMul + QT * D_;
    float* sV   = sK   + KT * KPAD;
    float* smk  = sV   + KT * KPAD;
    float* sA   = sK;

    const int t    = threadIdx.x;
    const int bh   = blockIdx.x;
    const int b    = bh / H_;
    const int q0   = blockIdx.y * QT;
    const int w    = t >> 5;
    const int lane = t & 31;
    const int kspl = lane >> 3;
    const int dhc  = lane & 7;

    const float* Qbase = &g_Q[(size_t)(bh * L_ + q0) * DH_];
    const float* Kbase = &g_K[(size_t)bh * L_ * DH_];
    const float* Vbase = &g_V[(size_t)bh * L_ * DH_];

    for (int i = t; i < QT * DH_ / 4; i += 256)
        *reinterpret_cast<float4*>(&sQ[i * 4]) =
            *reinterpret_cast<const float4*>(&Qbase[i * 4]);
    {
        int q = t >> 3, dd = t & 7;
        int ridx = (bh * D_ + dd) * L_ + q0 + q;
        sMul[q * 8 + dd] = g_w[b * D_ + dd] / g_S[ridx];
    }

    float ctx[4][8];
    #pragma unroll
    for (int qi = 0; qi < 4; qi++)
        #pragma unroll
        for (int j = 0; j < 8; j++) ctx[qi][j] = 0.f;

    for (int kt = 0; kt < L_; kt += KT) {
        __syncthreads();
        for (int i = t; i < KT * DH_ / 4; i += 256) {
            int k = i >> 4, c = (i & 15) * 4;
            *reinterpret_cast<float4*>(&sK[k * KPAD + c]) =
                *reinterpret_cast<const float4*>(&Kbase[(size_t)(kt + k) * DH_ + c]);
            *reinterpret_cast<float4*>(&sV[k * KPAD + c]) =
                *reinterpret_cast<const float4*>(&Vbase[(size_t)(kt + k) * DH_ + c]);
        }
        if (t < KT) smk[t] = mask[b * L_ + kt + t];
        __syncthreads();

        float acc[4][4];
        #pragma unroll
        for (int qi = 0; qi < 4; qi++)
            #pragma unroll
            for (int kj = 0; kj < 4; kj++) acc[qi][kj] = 0.f;

        float mk[4];
        #pragma unroll
        for (int kj = 0; kj < 4; kj++) mk[kj] = smk[lane + 32 * kj];

        #pragma unroll
        for (int dd = 0; dd < D_; dd++) {
            float q8[4][8], mu[4];
            #pragma unroll
            for (int qi = 0; qi < 4; qi++) {
                const float* qp = &sQ[(4 * w + qi) * DH_ + dd * 8];
                float4 qa = *reinterpret_cast<const float4*>(qp);
                float4 qb = *reinterpret_cast<const float4*>(qp + 4);
                q8[qi][0] = qa.x; q8[qi][1] = qa.y; q8[qi][2] = qa.z; q8[qi][3] = qa.w;
                q8[qi][4] = qb.x; q8[qi][5] = qb.y; q8[qi][6] = qb.z; q8[qi][7] = qb.w;
                mu[qi] = sMul[(4 * w + qi) * 8 + dd];
            }
            #pragma unroll
            for (int kj = 0; kj < 4; kj++) {
                const float* kp = &sK[(lane + 32 * kj) * KPAD + dd * 8];
                float4 ka  = *reinterpret_cast<const float4*>(kp);
                float4 kb4 = *reinterpret_cast<const float4*>(kp + 4);
                #pragma unroll
                for (int qi = 0; qi < 4; qi++) {
                    float s = q8[qi][0] * ka.x;
                    s = fmaf(q8[qi][1], ka.y, s);
                    s = fmaf(q8[qi][2], ka.z, s);
                    s = fmaf(q8[qi][3], ka.w, s);
                    s = fmaf(q8[qi][4], kb4.x, s);
                    s = fmaf(q8[qi][5], kb4.y, s);
                    s = fmaf(q8[qi][6], kb4.z, s);
                    s = fmaf(q8[qi][7], kb4.w, s);
                    s = fmaf(s, INV_SQRT_DS, mk[kj]);
                    acc[qi][kj] = fmaf(mu[qi], __expf(s), acc[qi][kj]);
                }
            }
        }

        #pragma unroll
        for (int qi = 0; qi < 4; qi++) {
            float* row = &out_attn[(size_t)(bh * L_ + q0 + 4 * w + qi) * L_ + kt];
            #pragma unroll
            for (int kj = 0; kj < 4; kj++)
                row[lane + 32 * kj] = acc[qi][kj];
        }

        __syncthreads();
        #pragma unroll
        for (int qi = 0; qi < 4; qi++)
            #pragma unroll
            for (int kj = 0; kj < 4; kj++)
                sA[(4 * w + qi) * APAD + lane + 32 * kj] = acc[qi][kj];
        __syncthreads();

        #pragma unroll
        for (int j = 0; j < 4; j++) {
            #pragma unroll
            for (int r = 0; r < 8; r++) {
                int k = 32 * j + 8 * kspl + r;
                float a0 = sA[(4 * w + 0) * APAD + k];
                float a1 = sA[(4 * w + 1) * APAD + k];
                float a2 = sA[(4 * w + 2) * APAD + k];
                float a3 = sA[(4 * w + 3) * APAD + k];
                const float* vp = &sV[k * KPAD + dhc * 4];
                float4 v0 = *reinterpret_cast<const float4*>(vp);
                float4 v1 = *reinterpret_cast<const float4*>(vp + 32);
                float av[4] = {a0, a1, a2, a3};
                #pragma unroll
                for (int qi = 0; qi < 4; qi++) {
                    ctx[qi][0] = fmaf(av[qi], v0.x, ctx[qi][0]);
                    ctx[qi][1] = fmaf(av[qi], v0.y, ctx[qi][1]);
                    ctx[qi][2] = fmaf(av[qi], v0.z, ctx[qi][2]);
                    ctx[qi][3] = fmaf(av[qi], v0.w, ctx[qi][3]);
                    ctx[qi][4] = fmaf(av[qi], v1.x, ctx[qi][4]);
                    ctx[qi][5] = fmaf(av[qi], v1.y, ctx[qi][5]);
                    ctx[qi][6] = fmaf(av[qi], v1.z, ctx[qi][6]);
                    ctx[qi][7] = fmaf(av[qi], v1.w, ctx[qi][7]);
                }
            }
        }
    }

    #pragma unroll
    for (int qi = 0; qi < 4; qi++)
        #pragma unroll
        for (int j = 0; j < 8; j++) {
            ctx[qi][j] += __shfl_xor_sync(0xffffffff, ctx[qi][j], 8);
            ctx[qi][j] += __shfl_xor_sync(0xffffffff, ctx[qi][j], 16);
        }

    {
        int qg = q0 + 4 * w + kspl;
        float* op = &out_ctx[(size_t)(b * L_ + qg) * E_ + (bh % H_) * DH_ + dhc * 4];
        *reinterpret_cast<float4*>(op) =
            make_float4(ctx[kspl][0], ctx[kspl][1], ctx[kspl][2], ctx[kspl][3]);
        *reinterpret_cast<float4*>(op + 32) =
            make_float4(ctx[kspl][4], ctx[kspl][5], ctx[kspl][6], ctx[kspl][7]);
    }
}

// ============================================================================
extern "C" void kernel_launch(void* const* d_in, const int* in_sizes, int n_in,
                              void* d_out, int out_size)
{
    const float* hs   = (const float*)d_in[0];
    const float* mask = (const float*)d_in[1];
    const float* Wq   = (const float*)d_in[2];
    const float* bq   = (const float*)d_in[3];
    const float* Wk   = (const float*)d_in[4];
    const float* bk   = (const float*)d_in[5];
    const float* Wv   = (const float*)d_in[6];
    const float* bv   = (const float*)d_in[7];

    float* out_ctx  = (float*)d_out;
    float* out_attn = out_ctx + (size_t)B_ * L_ * E_;

    const int nsplit = NX4 + 3 * NW4;
    split_kernel<<<(nsplit + 255) / 256, 256>>>(hs, Wq, Wk, Wv);

    cudaFuncSetAttribute(proj_mma_kernel,
                         cudaFuncAttributeMaxDynamicSharedMemorySize, PROJ_SMEM);
    proj_mma_kernel<<<dim3(E_ / 128, (B_ * L_) / 128, 3), 256, PROJ_SMEM>>>(bq, bk, bv);

    stats_kernel<<<dim3(B_ * H_ * D_, L_ / 32), 256>>>(mask);
    weights_kernel<<<1, 32>>>();

    const int smem_bytes = (QT * DH_ + QT * D_ + 2 * KT * KPAD + KT) * (int)sizeof(float);
    cudaFuncSetAttribute(attn_kernel, cudaFuncAttributeMaxDynamicSharedMemorySize, smem_bytes);
    attn_kernel<<<dim3(B_ * H_, L_ / QT), 256, smem_bytes>>>(mask, out_ctx, out_attn);
}

// round 10
// speedup vs baseline: 1.0667x; 1.0667x over previous
#include <cuda_runtime.h>
#include <cuda_bf16.h>
#include <math.h>
#include <stdint.h>

#define B_  2
#define L_  768
#define E_  768
#define H_  12
#define DH_ 64
#define D_  8
#define DS_ 8
#define INV_SQRT_DS 0.35355339059327373f
#define ALPHA_ 2.5f

// ---------------- scratch (static device globals; no allocation) -------------
__device__ float  g_Q[B_*H_*L_*DH_];
__device__ float  g_K[B_*H_*L_*DH_];
__device__ float  g_V[B_*H_*L_*DH_];
__device__ float  g_S[B_*H_*D_*L_];      // per (b,h,d,q): softmax denom (m=0)
__device__ double g_acc[B_*D_*4];        // sums over (h,q): var, max, hhi, ent
__device__ float  g_w[B_*D_];            // depth gate weights

// bf16 hi/lo splits for tensor-core projections
__device__ __nv_bfloat16 g_Xh[(size_t)B_*L_*E_];
__device__ __nv_bfloat16 g_Xl[(size_t)B_*L_*E_];
__device__ __nv_bfloat16 g_Wh[(size_t)3*E_*E_];
__device__ __nv_bfloat16 g_Wl[(size_t)3*E_*E_];

__device__ __forceinline__ uint32_t smem_u32(const void* p) {
    uint32_t a;
    asm("{ .reg .u64 t; cvta.to.shared.u64 t, %1; cvt.u32.u64 %0, t; }"
        : "=r"(a) : "l"(p));
    return a;
}

// packed f32x2 helpers (dual-lane fp32 FMA on one issue slot)
#define FMA2(d, a, b, c) \
    asm("fma.rn.f32x2 %0, %1, %2, %3;" : "=l"(d) : "l"(a), "l"(b), "l"(c))
#define PACK2(d, lo, hi) \
    asm("mov.b64 %0, {%1, %2};" : "=l"(d) : "f"(lo), "f"(hi))
#define UNPACK2(lo, hi, s) \
    asm("mov.b64 {%0, %1}, %2;" : "=f"(lo), "=f"(hi) : "l"(s))

// ============================================================================
// K0: split fp32 X and W into bf16 hi/lo; also zero g_acc.
// ============================================================================
#define NX4 ((B_*L_*E_) / 4)
#define NW4 ((E_*E_) / 4)

__global__ __launch_bounds__(256) void split_kernel(
    const float* __restrict__ X,
    const float* __restrict__ Wq, const float* __restrict__ Wk,
    const float* __restrict__ Wv)
{
    int idx = blockIdx.x * blockDim.x + threadIdx.x;
    if (blockIdx.x == 0 && threadIdx.x < B_*D_*4) g_acc[threadIdx.x] = 0.0;
    if (idx >= NX4 + 3 * NW4) return;

    const float* src;
    __nv_bfloat16 *dh, *dl;
    int off;
    if (idx < NX4) {
        src = X; dh = g_Xh; dl = g_Xl; off = idx * 4;
    } else {
        int j = idx - NX4;
        int w = j / NW4;
        off = (j - w * NW4) * 4;
        src = (w == 0) ? Wq : (w == 1) ? Wk : Wv;
        dh = g_Wh + (size_t)w * E_ * E_;
        dl = g_Wl + (size_t)w * E_ * E_;
    }
    float4 v = *reinterpret_cast<const float4*>(&src[off]);
    float f[4] = {v.x, v.y, v.z, v.w};
    ushort4 uh, ul;
    unsigned short* ph = &uh.x;
    unsigned short* pl = &ul.x;
    #pragma unroll
    for (int i = 0; i < 4; i++) {
        __nv_bfloat16 hi = __float2bfloat16(f[i]);
        __nv_bfloat16 lo = __float2bfloat16(f[i] - __bfloat162float(hi));
        ph[i] = __bfloat16_as_ushort(hi);
        pl[i] = __bfloat16_as_ushort(lo);
    }
    *reinterpret_cast<ushort4*>(&dh[off]) = uh;
    *reinterpret_cast<ushort4*>(&dl[off]) = ul;
}

// ============================================================================
// K1: mma.sync bf16 projection GEMM (round-8 version: measured best).
// C[1536,768] = [Xh|Xh|Xl] @ [[Wh],[Wl],[Wh]]  (K = 3*768, phase-indexed).
// CTA tile 128x128, 8 warps (4m x 2n), warp tile 32x64 = 2x8 m16n8k16.
// BK=32 double-buffered smem, reg prefetch.
// ============================================================================
#define SA 40    // A smem row stride (bf16): 80B -> ldmatrix conflict-free
#define SB 136   // B smem row stride (bf16): 272B -> conflict-free
#define KITERS 72  // 2304 / 32

__global__ __launch_bounds__(256) void proj_mma_kernel(
    const float* __restrict__ bq, const float* __restrict__ bk,
    const float* __restrict__ bv)
{
    __shared__ __align__(16) __nv_bfloat16 As[2][128 * SA];
    __shared__ __align__(16) __nv_bfloat16 Bs[2][32 * SB];

    const int t = threadIdx.x, warp = t >> 5, lane = t & 31;
    const int wm = warp & 3, wn = warp >> 2;
    const int z = blockIdx.z;
    const int row0 = blockIdx.y * 128, col0 = blockIdx.x * 128;

    const __nv_bfloat16* Wh = g_Wh + (size_t)z * E_ * E_;
    const __nv_bfloat16* Wl = g_Wl + (size_t)z * E_ * E_;
    const float* bias = (z == 0) ? bq : (z == 1) ? bk : bv;
    float* out = (z == 0) ? g_Q : (z == 1) ? g_K : g_V;

    float acc[2][8][4];
    #pragma unroll
    for (int mt = 0; mt < 2; mt++)
        #pragma unroll
        for (int nt = 0; nt < 8; nt++)
            #pragma unroll
            for (int i = 0; i < 4; i++) acc[mt][nt][i] = 0.f;

    const int ar0 = t >> 2, ak0 = (t & 3) * 8;
    const int bk0 = t >> 4, bn0 = (t & 15) * 8;

    uint4 ra0, ra1, rb0, rb1;
    ra0 = *reinterpret_cast<const uint4*>(&g_Xh[(size_t)(row0 + ar0) * E_ + ak0]);
    ra1 = *reinterpret_cast<const uint4*>(&g_Xh[(size_t)(row0 + ar0 + 64) * E_ + ak0]);
    rb0 = *reinterpret_cast<const uint4*>(&Wh[(size_t)bk0 * E_ + col0 + bn0]);
    rb1 = *reinterpret_cast<const uint4*>(&Wh[(size_t)(bk0 + 16) * E_ + col0 + bn0]);

    int buf = 0;
    *reinterpret_cast<uint4*>(&As[0][ar0 * SA + ak0]) = ra0;
    *reinterpret_cast<uint4*>(&As[0][(ar0 + 64) * SA + ak0]) = ra1;
    *reinterpret_cast<uint4*>(&Bs[0][bk0 * SB + bn0]) = rb0;
    *reinterpret_cast<uint4*>(&Bs[0][(bk0 + 16) * SB + bn0]) = rb1;
    __syncthreads();

    for (int it = 0; it < KITERS; it++) {
        if (it + 1 < KITERS) {
            const int nit = it + 1;
            const int ph = nit / 24;
            const int k768 = (nit % 24) * 32;
            const __nv_bfloat16* Ap = (ph < 2) ? g_Xh : g_Xl;
            const __nv_bfloat16* Bp = (ph == 1) ? Wl : Wh;
            ra0 = *reinterpret_cast<const uint4*>(&Ap[(size_t)(row0 + ar0) * E_ + k768 + ak0]);
            ra1 = *reinterpret_cast<const uint4*>(&Ap[(size_t)(row0 + ar0 + 64) * E_ + k768 + ak0]);
            rb0 = *reinterpret_cast<const uint4*>(&Bp[(size_t)(k768 + bk0) * E_ + col0 + bn0]);
            rb1 = *reinterpret_cast<const uint4*>(&Bp[(size_t)(k768 + bk0 + 16) * E_ + col0 + bn0]);
        }

        #pragma unroll
        for (int ks = 0; ks < 2; ks++) {
            uint32_t a[2][4];
            #pragma unroll
            for (int mt = 0; mt < 2; mt++) {
                uint32_t addr = smem_u32(
                    &As[buf][(wm * 32 + mt * 16 + (lane & 15)) * SA + ks * 16 + (lane >> 4) * 8]);
                asm volatile("ldmatrix.sync.aligned.m8n8.x4.shared.b16 {%0,%1,%2,%3}, [%4];"
                    : "=r"(a[mt][0]), "=r"(a[mt][1]), "=r"(a[mt][2]), "=r"(a[mt][3])
                    : "r"(addr));
            }
            #pragma unroll
            for (int nt = 0; nt < 8; nt++) {
                uint32_t b0, b1;
                uint32_t baddr = smem_u32(
                    &Bs[buf][(ks * 16 + (lane & 15)) * SB + wn * 64 + nt * 8]);
                asm volatile("ldmatrix.sync.aligned.m8n8.x2.trans.shared.b16 {%0,%1}, [%2];"
                    : "=r"(b0), "=r"(b1) : "r"(baddr));
                #pragma unroll
                for (int mt = 0; mt < 2; mt++) {
                    asm volatile(
                        "mma.sync.aligned.m16n8k16.row.col.f32.bf16.bf16.f32 "
                        "{%0,%1,%2,%3}, {%4,%5,%6,%7}, {%8,%9}, {%0,%1,%2,%3};"
                        : "+f"(acc[mt][nt][0]), "+f"(acc[mt][nt][1]),
                          "+f"(acc[mt][nt][2]), "+f"(acc[mt][nt][3])
                        : "r"(a[mt][0]), "r"(a[mt][1]), "r"(a[mt][2]), "r"(a[mt][3]),
                          "r"(b0), "r"(b1));
                }
            }
        }
        __syncthreads();
        if (it + 1 < KITERS) {
            int nb = buf ^ 1;
            *reinterpret_cast<uint4*>(&As[nb][ar0 * SA + ak0]) = ra0;
            *reinterpret_cast<uint4*>(&As[nb][(ar0 + 64) * SA + ak0]) = ra1;
            *reinterpret_cast<uint4*>(&Bs[nb][bk0 * SB + bn0]) = rb0;
            *reinterpret_cast<uint4*>(&Bs[nb][(bk0 + 16) * SB + bn0]) = rb1;
            __syncthreads();
            buf = nb;
        }
    }

    #pragma unroll
    for (int mt = 0; mt < 2; mt++) {
        #pragma unroll
        for (int nt = 0; nt < 8; nt++) {
            int r = row0 + wm * 32 + mt * 16 + (lane >> 2);
            int c = col0 + wn * 64 + nt * 8 + (lane & 3) * 2;
            int h = c >> 6, dh = c & 63;
            float bz0 = bias[c], bz1 = bias[c + 1];
            #pragma unroll
            for (int half = 0; half < 2; half++) {
                int rr = r + half * 8;
                int b = rr / L_, l = rr % L_;
                float* op = &out[(size_t)((b * H_ + h) * L_ + l) * DH_ + dh];
                float2 v;
                v.x = acc[mt][nt][half * 2 + 0] + bz0;
                v.y = acc[mt][nt][half * 2 + 1] + bz1;
                *reinterpret_cast<float2*>(op) = v;
            }
        }
    }
}

// ============================================================================
// K2: branchless stats, m=0 for exp; f32x2-packed dot products.
// ============================================================================
__global__ __launch_bounds__(256) void stats_kernel(const float* __restrict__ mask)
{
    __shared__ float sk[L_ * 12];
    __shared__ float sq[32 * 8];
    __shared__ float smask[L_];
    __shared__ float sred[8][4];

    const int t = threadIdx.x;
    const int bhd = blockIdx.x;
    const int d = bhd & 7;
    const int h = (bhd >> 3) % H_;
    const int b = bhd / (8 * H_);
    const int q0 = blockIdx.y * 32;

    const float* Kbase = &g_K[(size_t)(b * H_ + h) * L_ * DH_ + d * 8];

    for (int i = t; i < L_ * 2; i += 256) {
        int k = i >> 1, half = (i & 1) * 4;
        *reinterpret_cast<float4*>(&sk[k * 12 + half]) =
            *reinterpret_cast<const float4*>(&Kbase[(size_t)k * DH_ + half]);
    }
    sq[t] = g_Q[(size_t)((b * H_ + h) * L_ + q0 + (t >> 3)) * DH_ + d * 8 + (t & 7)];
    for (int i = t; i < L_; i += 256) smask[i] = mask[b * L_ + i];
    __syncthreads();

    const int warp = t >> 5, lane = t & 31;
    const int r0 = warp * 4;

    unsigned long long q2[4][4];
    #pragma unroll
    for (int r = 0; r < 4; r++) {
        ulonglong2 qa = *reinterpret_cast<const ulonglong2*>(&sq[(r0 + r) * 8]);
        ulonglong2 qb = *reinterpret_cast<const ulonglong2*>(&sq[(r0 + r) * 8 + 4]);
        q2[r][0] = qa.x; q2[r][1] = qa.y; q2[r][2] = qb.x; q2[r][3] = qb.y;
    }

    const unsigned long long z2 = 0ull;
    float S[4]  = {0.f, 0.f, 0.f, 0.f};
    float E1[4] = {0.f, 0.f, 0.f, 0.f};
    float E2[4] = {0.f, 0.f, 0.f, 0.f};
    float M[4]  = {-1e30f, -1e30f, -1e30f, -1e30f};

    for (int kb = 0; kb < L_; kb += 32) {
        int k = kb + lane;
        ulonglong2 ka = *reinterpret_cast<const ulonglong2*>(&sk[k * 12]);
        ulonglong2 kb2 = *reinterpret_cast<const ulonglong2*>(&sk[k * 12 + 4]);
        unsigned long long k2[4] = {ka.x, ka.y, kb2.x, kb2.y};
        float mk = smask[k];
        #pragma unroll
        for (int r = 0; r < 4; r++) {
            unsigned long long s2;
            FMA2(s2, q2[r][0], k2[0], z2);
            FMA2(s2, q2[r][1], k2[1], s2);
            FMA2(s2, q2[r][2], k2[2], s2);
            FMA2(s2, q2[r][3], k2[3], s2);
            float lo, hi;
            UNPACK2(lo, hi, s2);
            float s = fmaf(lo + hi, INV_SQRT_DS, mk);
            float e = __expf(s);
            S[r]  += e;
            E1[r]  = fmaf(e, s, E1[r]);
            E2[r]  = fmaf(e, e, E2[r]);
            M[r]   = fmaxf(M[r], s);
        }
    }

    #pragma unroll
    for (int r = 0; r < 4; r++) {
        #pragma unroll
        for (int off = 16; off > 0; off >>= 1) {
            S[r]  += __shfl_xor_sync(0xffffffff, S[r],  off);
            E1[r] += __shfl_xor_sync(0xffffffff, E1[r], off);
            E2[r] += __shfl_xor_sync(0xffffffff, E2[r], off);
            M[r]   = fmaxf(M[r], __shfl_xor_sync(0xffffffff, M[r], off));
        }
    }

    if (lane == 0) {
        float psum[4] = {0.f, 0.f, 0.f, 0.f};
        #pragma unroll
        for (int r = 0; r < 4; r++) {
            int row  = q0 + r0 + r;
            int ridx = ((b * H_ + h) * D_ + d) * L_ + row;
            g_S[ridx] = S[r];
            float inv  = 1.0f / S[r];
            float maxp = __expf(M[r]) * inv;
            float hhi  = E2[r] * inv * inv;
            float var  = (hhi - (1.0f / (float)L_)) * (1.0f / (float)(L_ - 1));
            float ent  = __logf(S[r]) - E1[r] * inv;
            psum[0] += var; psum[1] += maxp; psum[2] += hhi; psum[3] += ent;
        }
        #pragma unroll
        for (int i = 0; i < 4; i++) sred[warp][i] = psum[i];
    }
    __syncthreads();
    if (t == 0) {
        double tot[4] = {0, 0, 0, 0};
        #pragma unroll
        for (int w = 0; w < 8; w++)
            #pragma unroll
            for (int i = 0; i < 4; i++) tot[i] += (double)sred[w][i];
        #pragma unroll
        for (int i = 0; i < 4; i++)
            atomicAdd(&g_acc[(b * D_ + d) * 4 + i], tot[i]);
    }
}

// ============================================================================
// K3: depth gate weights.
// ============================================================================
__global__ void weights_kernel()
{
    int lane = threadIdx.x;
    int b  = (lane >> 3) & 1;
    int dd = lane & 7;
    const float scale = 1.0f / (float)(H_ * L_);
    float st[4];
    #pragma unroll
    for (int i = 0; i < 4; i++)
        st[i] = (float)(g_acc[(b * D_ + dd) * 4 + i]) * scale;

    float n[4];
    #pragma unroll
    for (int i = 0; i < 4; i++) {
        float vmin = st[i], vmax = st[i];
        #pragma unroll
        for (int off = 1; off < 8; off <<= 1) {
            vmin = fminf(vmin, __shfl_xor_sync(0xffffffff, vmin, off));
            vmax = fmaxf(vmax, __shfl_xor_sync(0xffffffff, vmax, off));
        }
        n[i] = (st[i] - vmin) / fmaxf(vmax - vmin, 1e-12f);
    }
    float score = 0.5f * n[0] + 0.3f * n[1] + 0.2f * n[2] - 0.4f * n[3];
    float smax = score;
    #pragma unroll
    for (int off = 1; off < 8; off <<= 1)
        smax = fmaxf(smax, __shfl_xor_sync(0xffffffff, smax, off));
    float e = __expf(ALPHA_ * (score - smax));
    float ssum = e;
    #pragma unroll
    for (int off = 1; off < 8; off <<= 1)
        ssum += __shfl_xor_sync(0xffffffff, ssum, off);
    if (lane < 16) g_w[b * D_ + dd] = e / ssum;
}

// ============================================================================
// K4: register-blocked 4q x 4k score tile; m=0; f32x2-packed dots + ctx.
// ============================================================================
#define QT 32
#define KT 128
#define KPAD 68
#define APAD 132

__global__ __launch_bounds__(256, 2) void attn_kernel(
    const float* __restrict__ mask,
    float* __restrict__ out_ctx,
    float* __restrict__ out_attn)
{
    extern __shared__ float smem_[];
    float* sQ   = smem_;
    float* sMul = sQ   + QT * DH_;
    float* sK   = sMul + QT * D_;
    float* sV   = sK   + KT * KPAD;
    float* smk  = sV   + KT * KPAD;
    float* sA   = sK;

    const int t    = threadIdx.x;
    const int bh   = blockIdx.x;
    const int b    = bh / H_;
    const int q0   = blockIdx.y * QT;
    const int w    = t >> 5;
    const int lane = t & 31;
    const int kspl = lane >> 3;
    const int dhc  = lane & 7;

    const float* Qbase = &g_Q[(size_t)(bh * L_ + q0) * DH_];
    const float* Kbase = &g_K[(size_t)bh * L_ * DH_];
    const float* Vbase = &g_V[(size_t)bh * L_ * DH_];

    for (int i = t; i < QT * DH_ / 4; i += 256)
        *reinterpret_cast<float4*>(&sQ[i * 4]) =
            *reinterpret_cast<const float4*>(&Qbase[i * 4]);
    {
        int q = t >> 3, dd = t & 7;
        int ridx = (bh * D_ + dd) * L_ + q0 + q;
        sMul[q * 8 + dd] = g_w[b * D_ + dd] / g_S[ridx];
    }

    const unsigned long long z2 = 0ull;
    unsigned long long ctx2[4][4];
    #pragma unroll
    for (int qi = 0; qi < 4; qi++)
        #pragma unroll
        for (int j = 0; j < 4; j++) ctx2[qi][j] = 0ull;

    for (int kt = 0; kt < L_; kt += KT) {
        __syncthreads();
        for (int i = t; i < KT * DH_ / 4; i += 256) {
            int k = i >> 4, c = (i & 15) * 4;
            *reinterpret_cast<float4*>(&sK[k * KPAD + c]) =
                *reinterpret_cast<const float4*>(&Kbase[(size_t)(kt + k) * DH_ + c]);
            *reinterpret_cast<float4*>(&sV[k * KPAD + c]) =
                *reinterpret_cast<const float4*>(&Vbase[(size_t)(kt + k) * DH_ + c]);
        }
        if (t < KT) smk[t] = mask[b * L_ + kt + t];
        __syncthreads();

        float acc[4][4];
        #pragma unroll
        for (int qi = 0; qi < 4; qi++)
            #pragma unroll
            for (int kj = 0; kj < 4; kj++) acc[qi][kj] = 0.f;

        float mk[4];
        #pragma unroll
        for (int kj = 0; kj < 4; kj++) mk[kj] = smk[lane + 32 * kj];

        #pragma unroll
        for (int dd = 0; dd < D_; dd++) {
            unsigned long long q2[4][4];
            float mu[4];
            #pragma unroll
            for (int qi = 0; qi < 4; qi++) {
                const float* qp = &sQ[(4 * w + qi) * DH_ + dd * 8];
                ulonglong2 qa = *reinterpret_cast<const ulonglong2*>(qp);
                ulonglong2 qb = *reinterpret_cast<const ulonglong2*>(qp + 4);
                q2[qi][0] = qa.x; q2[qi][1] = qa.y;
                q2[qi][2] = qb.x; q2[qi][3] = qb.y;
                mu[qi] = sMul[(4 * w + qi) * 8 + dd];
            }
            #pragma unroll
            for (int kj = 0; kj < 4; kj++) {
                const float* kp = &sK[(lane + 32 * kj) * KPAD + dd * 8];
                ulonglong2 ka = *reinterpret_cast<const ulonglong2*>(kp);
                ulonglong2 kb2 = *reinterpret_cast<const ulonglong2*>(kp + 4);
                unsigned long long k2[4] = {ka.x, ka.y, kb2.x, kb2.y};
                #pragma unroll
                for (int qi = 0; qi < 4; qi++) {
                    unsigned long long s2;
                    FMA2(s2, q2[qi][0], k2[0], z2);
                    FMA2(s2, q2[qi][1], k2[1], s2);
                    FMA2(s2, q2[qi][2], k2[2], s2);
                    FMA2(s2, q2[qi][3], k2[3], s2);
                    float lo, hi;
                    UNPACK2(lo, hi, s2);
                    float s = fmaf(lo + hi, INV_SQRT_DS, mk[kj]);
                    acc[qi][kj] = fmaf(mu[qi], __expf(s), acc[qi][kj]);
                }
            }
        }

        #pragma unroll
        for (int qi = 0; qi < 4; qi++) {
            float* row = &out_attn[(size_t)(bh * L_ + q0 + 4 * w + qi) * L_ + kt];
            #pragma unroll
            for (int kj = 0; kj < 4; kj++)
                row[lane + 32 * kj] = acc[qi][kj];
        }

        __syncthreads();
        #pragma unroll
        for (int qi = 0; qi < 4; qi++)
            #pragma unroll
            for (int kj = 0; kj < 4; kj++)
                sA[(4 * w + qi) * APAD + lane + 32 * kj] = acc[qi][kj];
        __syncthreads();

        #pragma unroll
        for (int j = 0; j < 4; j++) {
            #pragma unroll
            for (int r = 0; r < 8; r++) {
                int k = 32 * j + 8 * kspl + r;
                float a_[4];
                a_[0] = sA[(4 * w + 0) * APAD + k];
                a_[1] = sA[(4 * w + 1) * APAD + k];
                a_[2] = sA[(4 * w + 2) * APAD + k];
                a_[3] = sA[(4 * w + 3) * APAD + k];
                const float* vp = &sV[k * KPAD + dhc * 4];
                ulonglong2 v01 = *reinterpret_cast<const ulonglong2*>(vp);
                ulonglong2 v23 = *reinterpret_cast<const ulonglong2*>(vp + 32);
                #pragma unroll
                for (int qi = 0; qi < 4; qi++) {
                    unsigned long long av2;
                    PACK2(av2, a_[qi], a_[qi]);
                    FMA2(ctx2[qi][0], av2, v01.x, ctx2[qi][0]);
                    FMA2(ctx2[qi][1], av2, v01.y, ctx2[qi][1]);
                    FMA2(ctx2[qi][2], av2, v23.x, ctx2[qi][2]);
                    FMA2(ctx2[qi][3], av2, v23.y, ctx2[qi][3]);
                }
            }
        }
    }

    // unpack ctx pairs, reduce over kspl (lane bits 3,4), write out
    float ctx[4][8];
    #pragma unroll
    for (int qi = 0; qi < 4; qi++)
        #pragma unroll
        for (int j = 0; j < 4; j++)
            UNPACK2(ctx[qi][j * 2], ctx[qi][j * 2 + 1], ctx2[qi][j]);

    #pragma unroll
    for (int qi = 0; qi < 4; qi++)
        #pragma unroll
        for (int j = 0; j < 8; j++) {
            ctx[qi][j] += __shfl_xor_sync(0xffffffff, ctx[qi][j], 8);
            ctx[qi][j] += __shfl_xor_sync(0xffffffff, ctx[qi][j], 16);
        }

    {
        int qg = q0 + 4 * w + kspl;
        float* op = &out_ctx[(size_t)(b * L_ + qg) * E_ + (bh % H_) * DH_ + dhc * 4];
        *reinterpret_cast<float4*>(op) =
            make_float4(ctx[kspl][0], ctx[kspl][1], ctx[kspl][2], ctx[kspl][3]);
        *reinterpret_cast<float4*>(op + 32) =
            make_float4(ctx[kspl][4], ctx[kspl][5], ctx[kspl][6], ctx[kspl][7]);
    }
}

// ============================================================================
extern "C" void kernel_launch(void* const* d_in, const int* in_sizes, int n_in,
                              void* d_out, int out_size)
{
    const float* hs   = (const float*)d_in[0];
    const float* mask = (const float*)d_in[1];
    const float* Wq   = (const float*)d_in[2];
    const float* bq   = (const float*)d_in[3];
    const float* Wk   = (const float*)d_in[4];
    const float* bk   = (const float*)d_in[5];
    const float* Wv   = (const float*)d_in[6];
    const float* bv   = (const float*)d_in[7];

    float* out_ctx  = (float*)d_out;
    float* out_attn = out_ctx + (size_t)B_ * L_ * E_;

    const int nsplit = NX4 + 3 * NW4;
    split_kernel<<<(nsplit + 255) / 256, 256>>>(hs, Wq, Wk, Wv);

    proj_mma_kernel<<<dim3(E_ / 128, (B_ * L_) / 128, 3), 256>>>(bq, bk, bv);

    stats_kernel<<<dim3(B_ * H_ * D_, L_ / 32), 256>>>(mask);
    weights_kernel<<<1, 32>>>();

    const int smem_bytes = (QT * DH_ + QT * D_ + 2 * KT * KPAD + KT) * (int)sizeof(float);
    cudaFuncSetAttribute(attn_kernel, cudaFuncAttributeMaxDynamicSharedMemorySize, smem_bytes);
    attn_kernel<<<dim3(B_ * H_, L_ / QT), 256, smem_bytes>>>(mask, out_ctx, out_attn);
}

// round 11
// speedup vs baseline: 1.1715x; 1.0982x over previous
#include <cuda_runtime.h>
#include <cuda_bf16.h>
#include <math.h>
#include <stdint.h>

#define B_  2
#define L_  768
#define E_  768
#define H_  12
#define DH_ 64
#define D_  8
#define DS_ 8
#define INV_SQRT_DS 0.35355339059327373f
#define ALPHA_ 2.5f

// ---------------- scratch (static device globals; no allocation) -------------
__device__ float  g_Q[B_*H_*L_*DH_];
__device__ float  g_K[B_*H_*L_*DH_];
__device__ float  g_V[B_*H_*L_*DH_];
__device__ float  g_S[B_*H_*D_*L_];      // per (b,h,d,q): softmax denom (m=0)
__device__ double g_acc[B_*D_*4];        // sums over (h,q): var, max, hhi, ent
__device__ float  g_w[B_*D_];            // depth gate weights

__device__ __forceinline__ uint32_t smem_u32(const void* p) {
    uint32_t a;
    asm("{ .reg .u64 t; cvta.to.shared.u64 t, %1; cvt.u32.u64 %0, t; }"
        : "=r"(a) : "l"(p));
    return a;
}

// packed f32x2 helpers (dual-lane fp32 FMA on one issue slot)
#define FMA2(d, a, b, c) \
    asm("fma.rn.f32x2 %0, %1, %2, %3;" : "=l"(d) : "l"(a), "l"(b), "l"(c))
#define PACK2(d, lo, hi) \
    asm("mov.b64 %0, {%1, %2};" : "=l"(d) : "f"(lo), "f"(hi))
#define UNPACK2(lo, hi, s) \
    asm("mov.b64 {%0, %1}, %2;" : "=f"(lo), "=f"(hi) : "l"(s))

// ============================================================================
// K1 (v3): fused split + mma.sync bf16 projection GEMM.
// out = X @ W + b via 3-product fp32 split computed in-register:
//   C += Ah·Bh + Ah·Bl + Al·Bh  per 32-k chunk (24 iters over K=768).
// Grid (12 n-blocks[64], 12 m-blocks[128], 3 z).  256 thr, 8 warps (4m x 2n),
// warp tile 32x32 = 2x4 m16n8k16.  Double-buffered smem, reg prefetch (fp32).
// ============================================================================
#define PSA 40    // A smem row stride (bf16): 80B  -> ldmatrix conflict-free
#define PSB 72    // B smem row stride (bf16): 144B -> 9x16B, conflict-free
#define PBUF (128*PSA + 128*PSA + 32*PSB + 32*PSB)   // bf16 elems per buffer
#define PROJ_SMEM (2 * PBUF * 2)                      // bytes

__device__ __forceinline__ void cvt_split4(float4 v, ushort4& h, ushort4& l) {
    float f[4] = {v.x, v.y, v.z, v.w};
    unsigned short* ph = &h.x;
    unsigned short* pl = &l.x;
    #pragma unroll
    for (int i = 0; i < 4; i++) {
        __nv_bfloat16 hi = __float2bfloat16(f[i]);
        ph[i] = __bfloat16_as_ushort(hi);
        pl[i] = __bfloat16_as_ushort(__float2bfloat16(f[i] - __bfloat162float(hi)));
    }
}

__global__ __launch_bounds__(256) void proj_mma_kernel(
    const float* __restrict__ X,
    const float* __restrict__ Wq, const float* __restrict__ bq,
    const float* __restrict__ Wk, const float* __restrict__ bk,
    const float* __restrict__ Wv, const float* __restrict__ bv)
{
    extern __shared__ __align__(16) __nv_bfloat16 smp[];

    const int t = threadIdx.x, warp = t >> 5, lane = t & 31;
    const int wm = warp & 3, wn = warp >> 2;
    const int z = blockIdx.z;
    const int row0 = blockIdx.y * 128, col0 = blockIdx.x * 64;

    if (blockIdx.x == 0 && blockIdx.y == 0 && z == 0 && t < B_*D_*4)
        g_acc[t] = 0.0;

    const float* W   = (z == 0) ? Wq : (z == 1) ? Wk : Wv;
    const float* bias = (z == 0) ? bq : (z == 1) ? bk : bv;
    float* out = (z == 0) ? g_Q : (z == 1) ? g_K : g_V;

    // load mappings: A 128x32 fp32 = 1024 float4 (4/thr); B 32x64 = 512 (2/thr)
    int ar[4], ak[4], br[2], bn[2];
    #pragma unroll
    for (int j = 0; j < 4; j++) { int c = t + j * 256; ar[j] = c >> 3; ak[j] = (c & 7) * 4; }
    #pragma unroll
    for (int j = 0; j < 2; j++) { int c = t + j * 256; br[j] = c >> 4; bn[j] = (c & 15) * 4; }

    float4 raf[4], rbf[2];
    auto ld_regs = [&](int kk) {
        #pragma unroll
        for (int j = 0; j < 4; j++)
            raf[j] = *reinterpret_cast<const float4*>(&X[(size_t)(row0 + ar[j]) * E_ + kk + ak[j]]);
        #pragma unroll
        for (int j = 0; j < 2; j++)
            rbf[j] = *reinterpret_cast<const float4*>(&W[(size_t)(kk + br[j]) * E_ + col0 + bn[j]]);
    };
    auto st_smem = [&](int buf) {
        __nv_bfloat16* Ah = smp + buf * PBUF;
        __nv_bfloat16* Al = Ah + 128 * PSA;
        __nv_bfloat16* Bh = Al + 128 * PSA;
        __nv_bfloat16* Bl = Bh + 32 * PSB;
        #pragma unroll
        for (int j = 0; j < 4; j++) {
            ushort4 h, l;
            cvt_split4(raf[j], h, l);
            *reinterpret_cast<ushort4*>(&Ah[ar[j] * PSA + ak[j]]) = h;
            *reinterpret_cast<ushort4*>(&Al[ar[j] * PSA + ak[j]]) = l;
        }
        #pragma unroll
        for (int j = 0; j < 2; j++) {
            ushort4 h, l;
            cvt_split4(rbf[j], h, l);
            *reinterpret_cast<ushort4*>(&Bh[br[j] * PSB + bn[j]]) = h;
            *reinterpret_cast<ushort4*>(&Bl[br[j] * PSB + bn[j]]) = l;
        }
    };

    float acc[2][4][4];
    #pragma unroll
    for (int mt = 0; mt < 2; mt++)
        #pragma unroll
        for (int nt = 0; nt < 4; nt++)
            #pragma unroll
            for (int i = 0; i < 4; i++) acc[mt][nt][i] = 0.f;

    ld_regs(0);
    st_smem(0);
    __syncthreads();

    int buf = 0;
    for (int it = 0; it < 24; it++) {
        if (it + 1 < 24) ld_regs((it + 1) * 32);

        const __nv_bfloat16* Ah = smp + buf * PBUF;
        const __nv_bfloat16* Al = Ah + 128 * PSA;
        const __nv_bfloat16* Bh = Al + 128 * PSA;
        const __nv_bfloat16* Bl = Bh + 32 * PSB;

        #pragma unroll
        for (int ks = 0; ks < 2; ks++) {
            uint32_t ah[2][4], al[2][4];
            #pragma unroll
            for (int mt = 0; mt < 2; mt++) {
                int arow = wm * 32 + mt * 16 + (lane & 15);
                int acol = ks * 16 + (lane >> 4) * 8;
                uint32_t ad = smem_u32(&Ah[arow * PSA + acol]);
                asm volatile("ldmatrix.sync.aligned.m8n8.x4.shared.b16 {%0,%1,%2,%3}, [%4];"
                    : "=r"(ah[mt][0]), "=r"(ah[mt][1]), "=r"(ah[mt][2]), "=r"(ah[mt][3])
                    : "r"(ad));
                uint32_t ad2 = smem_u32(&Al[arow * PSA + acol]);
                asm volatile("ldmatrix.sync.aligned.m8n8.x4.shared.b16 {%0,%1,%2,%3}, [%4];"
                    : "=r"(al[mt][0]), "=r"(al[mt][1]), "=r"(al[mt][2]), "=r"(al[mt][3])
                    : "r"(ad2));
            }
            #pragma unroll
            for (int nt = 0; nt < 4; nt++) {
                int brow = ks * 16 + (lane & 15);
                int bcol = wn * 32 + nt * 8;
                uint32_t bh0, bh1, bl0, bl1;
                uint32_t bd = smem_u32(&Bh[brow * PSB + bcol]);
                asm volatile("ldmatrix.sync.aligned.m8n8.x2.trans.shared.b16 {%0,%1}, [%2];"
                    : "=r"(bh0), "=r"(bh1) : "r"(bd));
                uint32_t bd2 = smem_u32(&Bl[brow * PSB + bcol]);
                asm volatile("ldmatrix.sync.aligned.m8n8.x2.trans.shared.b16 {%0,%1}, [%2];"
                    : "=r"(bl0), "=r"(bl1) : "r"(bd2));
                #pragma unroll
                for (int mt = 0; mt < 2; mt++) {
                    asm volatile(
                        "mma.sync.aligned.m16n8k16.row.col.f32.bf16.bf16.f32 "
                        "{%0,%1,%2,%3}, {%4,%5,%6,%7}, {%8,%9}, {%0,%1,%2,%3};"
                        : "+f"(acc[mt][nt][0]), "+f"(acc[mt][nt][1]),
                          "+f"(acc[mt][nt][2]), "+f"(acc[mt][nt][3])
                        : "r"(ah[mt][0]), "r"(ah[mt][1]), "r"(ah[mt][2]), "r"(ah[mt][3]),
                          "r"(bh0), "r"(bh1));
                    asm volatile(
                        "mma.sync.aligned.m16n8k16.row.col.f32.bf16.bf16.f32 "
                        "{%0,%1,%2,%3}, {%4,%5,%6,%7}, {%8,%9}, {%0,%1,%2,%3};"
                        : "+f"(acc[mt][nt][0]), "+f"(acc[mt][nt][1]),
                          "+f"(acc[mt][nt][2]), "+f"(acc[mt][nt][3])
                        : "r"(ah[mt][0]), "r"(ah[mt][1]), "r"(ah[mt][2]), "r"(ah[mt][3]),
                          "r"(bl0), "r"(bl1));
                    asm volatile(
                        "mma.sync.aligned.m16n8k16.row.col.f32.bf16.bf16.f32 "
                        "{%0,%1,%2,%3}, {%4,%5,%6,%7}, {%8,%9}, {%0,%1,%2,%3};"
                        : "+f"(acc[mt][nt][0]), "+f"(acc[mt][nt][1]),
                          "+f"(acc[mt][nt][2]), "+f"(acc[mt][nt][3])
                        : "r"(al[mt][0]), "r"(al[mt][1]), "r"(al[mt][2]), "r"(al[mt][3]),
                          "r"(bh0), "r"(bh1));
                }
            }
        }
        __syncthreads();
        if (it + 1 < 24) {
            st_smem(buf ^ 1);
            __syncthreads();
            buf ^= 1;
        }
    }

    // epilogue: bias + store to [b,h,l,dh];  h == blockIdx.x (64-col tiles)
    #pragma unroll
    for (int mt = 0; mt < 2; mt++) {
        #pragma unroll
        for (int nt = 0; nt < 4; nt++) {
            int r = row0 + wm * 32 + mt * 16 + (lane >> 2);
            int c = col0 + wn * 32 + nt * 8 + (lane & 3) * 2;
            int h = c >> 6, dh = c & 63;
            float bz0 = bias[c], bz1 = bias[c + 1];
            #pragma unroll
            for (int half = 0; half < 2; half++) {
                int rr = r + half * 8;
                int b = rr / L_, l = rr % L_;
                float* op = &out[(size_t)((b * H_ + h) * L_ + l) * DH_ + dh];
                float2 v;
                v.x = acc[mt][nt][half * 2 + 0] + bz0;
                v.y = acc[mt][nt][half * 2 + 1] + bz1;
                *reinterpret_cast<float2*>(op) = v;
            }
        }
    }
}

// ============================================================================
// K2: branchless stats, m=0 for exp; f32x2-packed dot products.
// ============================================================================
__global__ __launch_bounds__(256) void stats_kernel(const float* __restrict__ mask)
{
    __shared__ float sk[L_ * 12];
    __shared__ float sq[32 * 8];
    __shared__ float smask[L_];
    __shared__ float sred[8][4];

    const int t = threadIdx.x;
    const int bhd = blockIdx.x;
    const int d = bhd & 7;
    const int h = (bhd >> 3) % H_;
    const int b = bhd / (8 * H_);
    const int q0 = blockIdx.y * 32;

    const float* Kbase = &g_K[(size_t)(b * H_ + h) * L_ * DH_ + d * 8];

    for (int i = t; i < L_ * 2; i += 256) {
        int k = i >> 1, half = (i & 1) * 4;
        *reinterpret_cast<float4*>(&sk[k * 12 + half]) =
            *reinterpret_cast<const float4*>(&Kbase[(size_t)k * DH_ + half]);
    }
    sq[t] = g_Q[(size_t)((b * H_ + h) * L_ + q0 + (t >> 3)) * DH_ + d * 8 + (t & 7)];
    for (int i = t; i < L_; i += 256) smask[i] = mask[b * L_ + i];
    __syncthreads();

    const int warp = t >> 5, lane = t & 31;
    const int r0 = warp * 4;

    unsigned long long q2[4][4];
    #pragma unroll
    for (int r = 0; r < 4; r++) {
        ulonglong2 qa = *reinterpret_cast<const ulonglong2*>(&sq[(r0 + r) * 8]);
        ulonglong2 qb = *reinterpret_cast<const ulonglong2*>(&sq[(r0 + r) * 8 + 4]);
        q2[r][0] = qa.x; q2[r][1] = qa.y; q2[r][2] = qb.x; q2[r][3] = qb.y;
    }

    const unsigned long long z2 = 0ull;
    float S[4]  = {0.f, 0.f, 0.f, 0.f};
    float E1[4] = {0.f, 0.f, 0.f, 0.f};
    float E2[4] = {0.f, 0.f, 0.f, 0.f};
    float M[4]  = {-1e30f, -1e30f, -1e30f, -1e30f};

    for (int kb = 0; kb < L_; kb += 32) {
        int k = kb + lane;
        ulonglong2 ka = *reinterpret_cast<const ulonglong2*>(&sk[k * 12]);
        ulonglong2 kb2 = *reinterpret_cast<const ulonglong2*>(&sk[k * 12 + 4]);
        unsigned long long k2[4] = {ka.x, ka.y, kb2.x, kb2.y};
        float mk = smask[k];
        #pragma unroll
        for (int r = 0; r < 4; r++) {
            unsigned long long s2;
            FMA2(s2, q2[r][0], k2[0], z2);
            FMA2(s2, q2[r][1], k2[1], s2);
            FMA2(s2, q2[r][2], k2[2], s2);
            FMA2(s2, q2[r][3], k2[3], s2);
            float lo, hi;
            UNPACK2(lo, hi, s2);
            float s = fmaf(lo + hi, INV_SQRT_DS, mk);
            float e = __expf(s);
            S[r]  += e;
            E1[r]  = fmaf(e, s, E1[r]);
            E2[r]  = fmaf(e, e, E2[r]);
            M[r]   = fmaxf(M[r], s);
        }
    }

    #pragma unroll
    for (int r = 0; r < 4; r++) {
        #pragma unroll
        for (int off = 16; off > 0; off >>= 1) {
            S[r]  += __shfl_xor_sync(0xffffffff, S[r],  off);
            E1[r] += __shfl_xor_sync(0xffffffff, E1[r], off);
            E2[r] += __shfl_xor_sync(0xffffffff, E2[r], off);
            M[r]   = fmaxf(M[r], __shfl_xor_sync(0xffffffff, M[r], off));
        }
    }

    if (lane == 0) {
        float psum[4] = {0.f, 0.f, 0.f, 0.f};
        #pragma unroll
        for (int r = 0; r < 4; r++) {
            int row  = q0 + r0 + r;
            int ridx = ((b * H_ + h) * D_ + d) * L_ + row;
            g_S[ridx] = S[r];
            float inv  = 1.0f / S[r];
            float maxp = __expf(M[r]) * inv;
            float hhi  = E2[r] * inv * inv;
            float var  = (hhi - (1.0f / (float)L_)) * (1.0f / (float)(L_ - 1));
            float ent  = __logf(S[r]) - E1[r] * inv;
            psum[0] += var; psum[1] += maxp; psum[2] += hhi; psum[3] += ent;
        }
        #pragma unroll
        for (int i = 0; i < 4; i++) sred[warp][i] = psum[i];
    }
    __syncthreads();
    if (t == 0) {
        double tot[4] = {0, 0, 0, 0};
        #pragma unroll
        for (int w = 0; w < 8; w++)
            #pragma unroll
            for (int i = 0; i < 4; i++) tot[i] += (double)sred[w][i];
        #pragma unroll
        for (int i = 0; i < 4; i++)
            atomicAdd(&g_acc[(b * D_ + d) * 4 + i], tot[i]);
    }
}

// ============================================================================
// K3: depth gate weights.
// ============================================================================
__global__ void weights_kernel()
{
    int lane = threadIdx.x;
    int b  = (lane >> 3) & 1;
    int dd = lane & 7;
    const float scale = 1.0f / (float)(H_ * L_);
    float st[4];
    #pragma unroll
    for (int i = 0; i < 4; i++)
        st[i] = (float)(g_acc[(b * D_ + dd) * 4 + i]) * scale;

    float n[4];
    #pragma unroll
    for (int i = 0; i < 4; i++) {
        float vmin = st[i], vmax = st[i];
        #pragma unroll
        for (int off = 1; off < 8; off <<= 1) {
            vmin = fminf(vmin, __shfl_xor_sync(0xffffffff, vmin, off));
            vmax = fmaxf(vmax, __shfl_xor_sync(0xffffffff, vmax, off));
        }
        n[i] = (st[i] - vmin) / fmaxf(vmax - vmin, 1e-12f);
    }
    float score = 0.5f * n[0] + 0.3f * n[1] + 0.2f * n[2] - 0.4f * n[3];
    float smax = score;
    #pragma unroll
    for (int off = 1; off < 8; off <<= 1)
        smax = fmaxf(smax, __shfl_xor_sync(0xffffffff, smax, off));
    float e = __expf(ALPHA_ * (score - smax));
    float ssum = e;
    #pragma unroll
    for (int off = 1; off < 8; off <<= 1)
        ssum += __shfl_xor_sync(0xffffffff, ssum, off);
    if (lane < 16) g_w[b * D_ + dd] = e / ssum;
}

// ============================================================================
// K4: register-blocked 4q x 4k score tile; m=0; f32x2-packed dots + ctx.
// ============================================================================
#define QT 32
#define KT 128
#define KPAD 68
#define APAD 132

__global__ __launch_bounds__(256, 2) void attn_kernel(
    const float* __restrict__ mask,
    float* __restrict__ out_ctx,
    float* __restrict__ out_attn)
{
    extern __shared__ float smem_[];
    float* sQ   = smem_;
    float* sMul = sQ   + QT * DH_;
    float* sK   = sMul + QT * D_;
    float* sV   = sK   + KT * KPAD;
    float* smk  = sV   + KT * KPAD;
    float* sA   = sK;

    const int t    = threadIdx.x;
    const int bh   = blockIdx.x;
    const int b    = bh / H_;
    const int q0   = blockIdx.y * QT;
    const int w    = t >> 5;
    const int lane = t & 31;
    const int kspl = lane >> 3;
    const int dhc  = lane & 7;

    const float* Qbase = &g_Q[(size_t)(bh * L_ + q0) * DH_];
    const float* Kbase = &g_K[(size_t)bh * L_ * DH_];
    const float* Vbase = &g_V[(size_t)bh * L_ * DH_];

    for (int i = t; i < QT * DH_ / 4; i += 256)
        *reinterpret_cast<float4*>(&sQ[i * 4]) =
            *reinterpret_cast<const float4*>(&Qbase[i * 4]);
    {
        int q = t >> 3, dd = t & 7;
        int ridx = (bh * D_ + dd) * L_ + q0 + q;
        sMul[q * 8 + dd] = g_w[b * D_ + dd] / g_S[ridx];
    }

    const unsigned long long z2 = 0ull;
    unsigned long long ctx2[4][4];
    #pragma unroll
    for (int qi = 0; qi < 4; qi++)
        #pragma unroll
        for (int j = 0; j < 4; j++) ctx2[qi][j] = 0ull;

    for (int kt = 0; kt < L_; kt += KT) {
        __syncthreads();
        for (int i = t; i < KT * DH_ / 4; i += 256) {
            int k = i >> 4, c = (i & 15) * 4;
            *reinterpret_cast<float4*>(&sK[k * KPAD + c]) =
                *reinterpret_cast<const float4*>(&Kbase[(size_t)(kt + k) * DH_ + c]);
            *reinterpret_cast<float4*>(&sV[k * KPAD + c]) =
                *reinterpret_cast<const float4*>(&Vbase[(size_t)(kt + k) * DH_ + c]);
        }
        if (t < KT) smk[t] = mask[b * L_ + kt + t];
        __syncthreads();

        float acc[4][4];
        #pragma unroll
        for (int qi = 0; qi < 4; qi++)
            #pragma unroll
            for (int kj = 0; kj < 4; kj++) acc[qi][kj] = 0.f;

        float mk[4];
        #pragma unroll
        for (int kj = 0; kj < 4; kj++) mk[kj] = smk[lane + 32 * kj];

        #pragma unroll
        for (int dd = 0; dd < D_; dd++) {
            unsigned long long q2[4][4];
            float mu[4];
            #pragma unroll
            for (int qi = 0; qi < 4; qi++) {
                const float* qp = &sQ[(4 * w + qi) * DH_ + dd * 8];
                ulonglong2 qa = *reinterpret_cast<const ulonglong2*>(qp);
                ulonglong2 qb = *reinterpret_cast<const ulonglong2*>(qp + 4);
                q2[qi][0] = qa.x; q2[qi][1] = qa.y;
                q2[qi][2] = qb.x; q2[qi][3] = qb.y;
                mu[qi] = sMul[(4 * w + qi) * 8 + dd];
            }
            #pragma unroll
            for (int kj = 0; kj < 4; kj++) {
                const float* kp = &sK[(lane + 32 * kj) * KPAD + dd * 8];
                ulonglong2 ka = *reinterpret_cast<const ulonglong2*>(kp);
                ulonglong2 kb2 = *reinterpret_cast<const ulonglong2*>(kp + 4);
                unsigned long long k2[4] = {ka.x, ka.y, kb2.x, kb2.y};
                #pragma unroll
                for (int qi = 0; qi < 4; qi++) {
                    unsigned long long s2;
                    FMA2(s2, q2[qi][0], k2[0], z2);
                    FMA2(s2, q2[qi][1], k2[1], s2);
                    FMA2(s2, q2[qi][2], k2[2], s2);
                    FMA2(s2, q2[qi][3], k2[3], s2);
                    float lo, hi;
                    UNPACK2(lo, hi, s2);
                    float s = fmaf(lo + hi, INV_SQRT_DS, mk[kj]);
                    acc[qi][kj] = fmaf(mu[qi], __expf(s), acc[qi][kj]);
                }
            }
        }

        #pragma unroll
        for (int qi = 0; qi < 4; qi++) {
            float* row = &out_attn[(size_t)(bh * L_ + q0 + 4 * w + qi) * L_ + kt];
            #pragma unroll
            for (int kj = 0; kj < 4; kj++)
                row[lane + 32 * kj] = acc[qi][kj];
        }

        __syncthreads();
        #pragma unroll
        for (int qi = 0; qi < 4; qi++)
            #pragma unroll
            for (int kj = 0; kj < 4; kj++)
                sA[(4 * w + qi) * APAD + lane + 32 * kj] = acc[qi][kj];
        __syncthreads();

        #pragma unroll
        for (int j = 0; j < 4; j++) {
            #pragma unroll
            for (int r = 0; r < 8; r++) {
                int k = 32 * j + 8 * kspl + r;
                float a_[4];
                a_[0] = sA[(4 * w + 0) * APAD + k];
                a_[1] = sA[(4 * w + 1) * APAD + k];
                a_[2] = sA[(4 * w + 2) * APAD + k];
                a_[3] = sA[(4 * w + 3) * APAD + k];
                const float* vp = &sV[k * KPAD + dhc * 4];
                ulonglong2 v01 = *reinterpret_cast<const ulonglong2*>(vp);
                ulonglong2 v23 = *reinterpret_cast<const ulonglong2*>(vp + 32);
                #pragma unroll
                for (int qi = 0; qi < 4; qi++) {
                    unsigned long long av2;
                    PACK2(av2, a_[qi], a_[qi]);
                    FMA2(ctx2[qi][0], av2, v01.x, ctx2[qi][0]);
                    FMA2(ctx2[qi][1], av2, v01.y, ctx2[qi][1]);
                    FMA2(ctx2[qi][2], av2, v23.x, ctx2[qi][2]);
                    FMA2(ctx2[qi][3], av2, v23.y, ctx2[qi][3]);
                }
            }
        }
    }

    float ctx[4][8];
    #pragma unroll
    for (int qi = 0; qi < 4; qi++)
        #pragma unroll
        for (int j = 0; j < 4; j++)
            UNPACK2(ctx[qi][j * 2], ctx[qi][j * 2 + 1], ctx2[qi][j]);

    #pragma unroll
    for (int qi = 0; qi < 4; qi++)
        #pragma unroll
        for (int j = 0; j < 8; j++) {
            ctx[qi][j] += __shfl_xor_sync(0xffffffff, ctx[qi][j], 8);
            ctx[qi][j] += __shfl_xor_sync(0xffffffff, ctx[qi][j], 16);
        }

    {
        int qg = q0 + 4 * w + kspl;
        float* op = &out_ctx[(size_t)(b * L_ + qg) * E_ + (bh % H_) * DH_ + dhc * 4];
        *reinterpret_cast<float4*>(op) =
            make_float4(ctx[kspl][0], ctx[kspl][1], ctx[kspl][2], ctx[kspl][3]);
        *reinterpret_cast<float4*>(op + 32) =
            make_float4(ctx[kspl][4], ctx[kspl][5], ctx[kspl][6], ctx[kspl][7]);
    }
}

// ============================================================================
extern "C" void kernel_launch(void* const* d_in, const int* in_sizes, int n_in,
                              void* d_out, int out_size)
{
    const float* hs   = (const float*)d_in[0];
    const float* mask = (const float*)d_in[1];
    const float* Wq   = (const float*)d_in[2];
    const float* bq   = (const float*)d_in[3];
    const float* Wk   = (const float*)d_in[4];
    const float* bk   = (const float*)d_in[5];
    const float* Wv   = (const float*)d_in[6];
    const float* bv   = (const float*)d_in[7];

    float* out_ctx  = (float*)d_out;
    float* out_attn = out_ctx + (size_t)B_ * L_ * E_;

    cudaFuncSetAttribute(proj_mma_kernel,
                         cudaFuncAttributeMaxDynamicSharedMemorySize, PROJ_SMEM);
    proj_mma_kernel<<<dim3(E_ / 64, (B_ * L_) / 128, 3), 256, PROJ_SMEM>>>(
        hs, Wq, bq, Wk, bk, Wv, bv);

    stats_kernel<<<dim3(B_ * H_ * D_, L_ / 32), 256>>>(mask);
    weights_kernel<<<1, 32>>>();

    const int smem_bytes = (QT * DH_ + QT * D_ + 2 * KT * KPAD + KT) * (int)sizeof(float);
    cudaFuncSetAttribute(attn_kernel, cudaFuncAttributeMaxDynamicSharedMemorySize, smem_bytes);
    attn_kernel<<<dim3(B_ * H_, L_ / QT), 256, smem_bytes>>>(mask, out_ctx, out_attn);
}